// round 11
// baseline (speedup 1.0000x reference)
#include <cuda_runtime.h>
#include <math.h>
#include <stdint.h>

// Scratch: Q1 ping-pong in both layouts. [B,S,S], B=4,S=160 -> 102400
#define MAXQ 102400
#define MAXR 1024
__device__ __align__(16) float g_q1 [2][MAXQ];   // Q1[b,m,h]
__device__ __align__(16) float g_q1T[2][MAXQ];   // Q1[b,h,m]
__device__ int   g_excl[MAXQ];     // per (b,h): excluded t list (mask[b,t,h]==0 || t==h)
__device__ int   g_ecnt[MAXR];     // per (b,h): list length

__device__ __forceinline__ uint32_t smem_u32(const void* p) {
    uint32_t a;
    asm("{ .reg .u64 t; cvta.to.shared.u64 t, %1; cvt.u32.u64 %0, t; }" : "=r"(a) : "l"(p));
    return a;
}
__device__ __forceinline__ void cp16(uint32_t dst, const void* src) {
    asm volatile("cp.async.cg.shared.global [%0], [%1], 16;" :: "r"(dst), "l"(src) : "memory");
}
__device__ __forceinline__ void cp_commit() {
    asm volatile("cp.async.commit_group;" ::: "memory");
}
template<int N> __device__ __forceinline__ void cp_wait() {
    asm volatile("cp.async.wait_group %0;" :: "n"(N) : "memory");
}

// Pre-pass: build per-(b,h) exclusion list.
__global__ void excl_build_kernel(const int* __restrict__ mask, int S)
{
    __shared__ int cnt;
    int t = threadIdx.x;
    int h = blockIdx.x % S;
    int b = blockIdx.x / S;
    int row = b * S + h;
    if (t == 0) cnt = 0;
    __syncthreads();
    if (t < S) {
        bool ex = (mask[(b * S + t) * S + h] == 0) || (t == h);
        if (ex) {
            int slot = atomicAdd(&cnt, 1);
            g_excl[row * S + slot] = t;
        }
    }
    __syncthreads();
    if (t == 0) g_ecnt[row] = cnt;
}

// ============================================================================
// cp.async pipelined kernel, compile-time S=160.
// Block = (b, m, quarter). 5 tiles x 8 h-rows, 3-stage ring, 256 threads.
// ============================================================================
template<int MODE, int SS>
__global__ void __launch_bounds__(256)
mfvi_cp(const float* __restrict__ se,
        const float* __restrict__ ss,
        const float* __restrict__ sc,
        const float* __restrict__ sg,
        const int* __restrict__ mask,
        float* __restrict__ out,
        int parity)
{
    constexpr int ROWS = 8;                 // h-rows per tile
    constexpr int NT   = 5;                 // tiles per block
    constexpr int NQ   = SS / (ROWS * NT);  // quarters (4)
    constexpr int NST  = 3;                 // pipeline stages
    constexpr int AE   = ROWS * SS;         // elems per array per tile (1280)
    constexpr int STG  = 4 * AE;            // floats per stage (ss,sc,sg,qa)
    constexpr int CH   = AE * 4 / 16;       // 16B chunks per array (320)

    int blk = blockIdx.x;
    int qtr = blk % NQ;
    int m   = (blk / NQ) % SS;
    int b   = blk / (NQ * SS);
    int h0b = qtr * ROWS * NT;              // first h-row of this block

    int tid  = threadIdx.x;
    int w    = tid >> 5;                    // warp = row in tile
    int lane = tid & 31;

    extern __shared__ float smbuf[];
    float* sm_row = smbuf;                  // Q1[b,m,t]   [SS]
    float* sm_col = smbuf + SS;             // Q1[b,t,m]   [SS]
    float* stages = smbuf + 2 * SS;         // NST x STG

    const float* __restrict__ q1_in  = g_q1 [parity & 1];
    const float* __restrict__ q1T_in = g_q1T[parity & 1];

    const long mbase = ((long)(b * SS + m)) * SS * SS;

    // issue tile k into stage s (all threads cooperate)
    auto issue = [&](int k, int s) {
        int h0 = h0b + k * ROWS;
        long soff = mbase + (long)h0 * SS;          // scores
        long qoff = ((long)(b * SS + h0)) * SS;     // q1T rows
        float* st = stages + s * STG;
        uint32_t a0 = smem_u32(st);
        uint32_t a1 = smem_u32(st + AE);
        uint32_t a2 = smem_u32(st + 2 * AE);
        uint32_t a3 = smem_u32(st + 3 * AE);
        for (int c = tid; c < CH; c += 256) {
            cp16(a0 + c * 16, (const char*)(ss + soff) + c * 16);
            cp16(a1 + c * 16, (const char*)(sc + soff) + c * 16);
            cp16(a2 + c * 16, (const char*)(sg + soff) + c * 16);
            if (MODE != 0)
                cp16(a3 + c * 16, (const char*)(q1T_in + qoff) + c * 16);
        }
    };

    // prologue: fill the ring
    issue(0, 0); cp_commit();
    issue(1, 1); cp_commit();
    issue(2, 2); cp_commit();

    if (MODE != 0) {   // m-constant q1 row/col (overlaps the async copies)
        int nv = SS >> 2;
        const float4* r4 = (const float4*)(q1_in  + (b * SS + m) * SS);
        const float4* c4 = (const float4*)(q1T_in + (b * SS + m) * SS);
        for (int i = tid; i < 2 * nv; i += 256) {
            if (i < nv) ((float4*)sm_row)[i] = r4[i];
            else        ((float4*)sm_col)[i - nv] = c4[i - nv];
        }
    }

    #pragma unroll 1
    for (int i = 0; i < NT; i++) {
        cp_wait<2>();          // tile i (group i) complete
        __syncthreads();

        int s = i % NST;
        int h = h0b + i * ROWS + w;
        const float* st   = stages + s * STG;
        const float* ss_r = st + w * SS;
        const float* sc_r = st + AE + w * SS;
        const float* sg_r = st + 2 * AE + w * SS;
        const float* qa_r = st + 3 * AE + w * SS;
        const float4* pss = (const float4*)ss_r;
        const float4* psc = (const float4*)sc_r;
        const float4* psg = (const float4*)sg_r;
        const float4* pqa = (const float4*)qa_r;
        const float4* prow = (const float4*)sm_row;
        const float4* pcol = (const float4*)sm_col;

        float acc = 0.f;
        #pragma unroll 2
        for (int v = lane; v < (SS >> 2); v += 32) {
            float4 a4 = pss[v];
            float4 c4 = psc[v];
            float4 g4 = psg[v];
            if (MODE == 0) {
                #pragma unroll
                for (int j = 0; j < 4; j++)
                    acc += (&a4.x)[j] + (&c4.x)[j] + (&g4.x)[j];
            } else {
                float4 qa = pqa[v];
                float4 vr = prow[v];
                float4 vc = pcol[v];
                #pragma unroll
                for (int j = 0; j < 4; j++) {
                    acc += (&a4.x)[j] * (&qa.x)[j];
                    acc += (&c4.x)[j] * (&vr.x)[j];
                    acc += (&g4.x)[j] * (&vc.x)[j];
                }
            }
        }

        #pragma unroll
        for (int off = 16; off; off >>= 1)
            acc += __shfl_down_sync(0xffffffffu, acc, off);

        if (lane == 0) {
            int idx = (b * SS + m) * SS + h;
            float f = 0.f;
            if (mask[idx] != 0) {
                if (MODE == 0) acc *= 0.5f;
                int row = b * SS + h;
                int cnt = g_ecnt[row];
                for (int e = 0; e < cnt; e++) {
                    int t = g_excl[row * SS + e];
                    if (MODE == 0)
                        acc -= 0.5f * (ss_r[t] + sc_r[t] + sg_r[t]);
                    else
                        acc -= ss_r[t] * qa_r[t]
                             + sc_r[t] * sm_row[t]
                             + sg_r[t] * sm_col[t];
                }
                if (m != h) {   // t == m exclusion
                    if (MODE == 0)
                        acc -= 0.5f * (ss_r[m] + sc_r[m] + sg_r[m]);
                    else
                        acc -= ss_r[m] * qa_r[m]
                             + sc_r[m] * sm_row[m]
                             + sg_r[m] * sm_col[m];
                }
                f = acc;
            }
            float q = se[idx] + f;
            if (MODE == 2) {
                out[(long)idx * 2 + 0] = 1.f / (1.f + expf(q));
                out[(long)idx * 2 + 1] = 1.f / (1.f + expf(-q));
            } else {
                float q1v = 1.f / (1.f + expf(-q));
                int ob = (parity ^ 1) & 1;
                g_q1 [ob][idx] = q1v;
                g_q1T[ob][(b * SS + h) * SS + m] = q1v;
            }
        }

        __syncthreads();                  // stage s fully consumed
        if (i + 3 < NT) issue(i + 3, s);  // refill (may be empty near tail)
        cp_commit();                      // one group per iteration, keeps counts aligned
    }
}

// ============================================================================
// Generic fallback (R8 kernel) for S != 160
// ============================================================================
template<int MODE>
__global__ void __launch_bounds__(256, 4)
mfvi_fallback(const float* __restrict__ se,
              const float* __restrict__ ss,
              const float* __restrict__ sc,
              const float* __restrict__ sg,
              const int* __restrict__ mask,
              float* __restrict__ out,
              int S, int parity)
{
    const int RW = 4, HT = 32;
    int ntile = (S + HT - 1) / HT;
    int blk = blockIdx.x;
    int htile = blk % ntile;
    int m     = (blk / ntile) % S;
    int b     = blk / (ntile * S);
    int warp = threadIdx.x >> 5, lane = threadIdx.x & 31;
    int g = lane >> 3, li = lane & 7;
    int h = htile * HT + warp * RW + g;

    extern __shared__ float smbuf[];
    float* sm_row = smbuf;
    float* sm_col = smbuf + S;

    const float* __restrict__ q1_in  = g_q1 [parity & 1];
    const float* __restrict__ q1T_in = g_q1T[parity & 1];

    if (MODE != 0) {
        int nv = S >> 2;
        const float4* r4 = (const float4*)(q1_in  + (b * S + m) * S);
        const float4* c4 = (const float4*)(q1T_in + (b * S + m) * S);
        for (int i = threadIdx.x; i < 2 * nv; i += blockDim.x) {
            if (i < nv) ((float4*)sm_row)[i] = r4[i];
            else        ((float4*)sm_col)[i - nv] = c4[i - nv];
        }
        __syncthreads();
    }

    bool valid = (h < S);
    int FV = S >> 2;
    const long sbase = (((long)(b * S + m)) * S + h) * S;
    const long hbase = ((long)(b * S + h)) * S;
    const float4* p_ss = (const float4*)(ss + sbase);
    const float4* p_sc = (const float4*)(sc + sbase);
    const float4* p_sg = (const float4*)(sg + sbase);
    const float4* p_qa = (const float4*)(q1T_in + hbase);
    const float4* srow = (const float4*)sm_row;
    const float4* scol = (const float4*)sm_col;

    float acc = 0.f;
    if (valid) {
        #pragma unroll 5
        for (int v = li; v < FV; v += 8) {
            float4 vss = __ldcs(p_ss + v);
            float4 vsc = __ldcs(p_sc + v);
            float4 vsg = __ldcs(p_sg + v);
            if (MODE == 0) {
                #pragma unroll
                for (int j = 0; j < 4; j++)
                    acc += (&vss.x)[j] + (&vsc.x)[j] + (&vsg.x)[j];
            } else {
                float4 vqa = p_qa[v];
                float4 vr  = srow[v];
                float4 vc  = scol[v];
                #pragma unroll
                for (int j = 0; j < 4; j++) {
                    acc += (&vss.x)[j] * (&vqa.x)[j];
                    acc += (&vsc.x)[j] * (&vr.x)[j];
                    acc += (&vsg.x)[j] * (&vc.x)[j];
                }
            }
        }
    }
    acc += __shfl_down_sync(0xffffffffu, acc, 4, 8);
    acc += __shfl_down_sync(0xffffffffu, acc, 2, 8);
    acc += __shfl_down_sync(0xffffffffu, acc, 1, 8);

    if (li == 0 && valid) {
        int idx = (b * S + m) * S + h;
        float f = 0.f;
        if (mask[idx] != 0) {
            if (MODE == 0) acc *= 0.5f;
            int row = b * S + h;
            int cnt = g_ecnt[row];
            for (int i = 0; i < cnt; i++) {
                int t = g_excl[row * S + i];
                if (MODE == 0)
                    acc -= 0.5f * (ss[sbase + t] + sc[sbase + t] + sg[sbase + t]);
                else
                    acc -= ss[sbase + t] * q1T_in[hbase + t]
                         + sc[sbase + t] * sm_row[t]
                         + sg[sbase + t] * sm_col[t];
            }
            if (m != h) {
                if (MODE == 0)
                    acc -= 0.5f * (ss[sbase + m] + sc[sbase + m] + sg[sbase + m]);
                else
                    acc -= ss[sbase + m] * q1T_in[hbase + m]
                         + sc[sbase + m] * sm_row[m]
                         + sg[sbase + m] * sm_col[m];
            }
            f = acc;
        }
        float q = se[idx] + f;
        if (MODE == 2) {
            out[(long)idx * 2 + 0] = 1.f / (1.f + expf(q));
            out[(long)idx * 2 + 1] = 1.f / (1.f + expf(-q));
        } else {
            float q1v = 1.f / (1.f + expf(-q));
            int ob = (parity ^ 1) & 1;
            g_q1 [ob][idx] = q1v;
            g_q1T[ob][(b * S + h) * S + m] = q1v;
        }
    }
}

extern "C" void kernel_launch(void* const* d_in, const int* in_sizes, int n_in,
                              void* d_out, int out_size)
{
    const float* se = (const float*)d_in[0];
    const float* ss = (const float*)d_in[1];
    const float* sc = (const float*)d_in[2];
    const float* sg = (const float*)d_in[3];
    const int* mask = (const int*)d_in[4];
    float* out = (float*)d_out;

    int BSS = in_sizes[0];                  // B*S*S
    int S = in_sizes[1] / BSS;              // (B*S^3)/(B*S^2)
    int B = BSS / (S * S);

    excl_build_kernel<<<B * S, (S + 31) & ~31>>>(mask, S);

    if (S == 160) {
        constexpr int SS_ = 160;
        // smem: 2*S (row/col) + 3 stages * 4 arrays * 8*S floats
        size_t smem = (2 * (size_t)SS_ + 3 * 4 * 8 * (size_t)SS_) * sizeof(float); // 62,720 B
        cudaFuncSetAttribute(mfvi_cp<0, SS_>, cudaFuncAttributeMaxDynamicSharedMemorySize, (int)smem);
        cudaFuncSetAttribute(mfvi_cp<1, SS_>, cudaFuncAttributeMaxDynamicSharedMemorySize, (int)smem);
        cudaFuncSetAttribute(mfvi_cp<2, SS_>, cudaFuncAttributeMaxDynamicSharedMemorySize, (int)smem);
        dim3 grid(B * SS_ * 4);   // (b, m, quarter)
        mfvi_cp<0, SS_><<<grid, 256, smem>>>(se, ss, sc, sg, mask, out, 1);
        mfvi_cp<1, SS_><<<grid, 256, smem>>>(se, ss, sc, sg, mask, out, 0);
        mfvi_cp<2, SS_><<<grid, 256, smem>>>(se, ss, sc, sg, mask, out, 1);
    } else {
        int ntile = (S + 31) / 32;
        dim3 grid(B * S * ntile);
        size_t smem = 2 * (size_t)S * sizeof(float);
        mfvi_fallback<0><<<grid, 256, smem>>>(se, ss, sc, sg, mask, out, S, 1);
        mfvi_fallback<1><<<grid, 256, smem>>>(se, ss, sc, sg, mask, out, S, 0);
        mfvi_fallback<2><<<grid, 256, smem>>>(se, ss, sc, sg, mask, out, S, 1);
    }
}

// round 12
// speedup vs baseline: 1.8352x; 1.8352x over previous
#include <cuda_runtime.h>
#include <math.h>
#include <stdint.h>

// Scratch: Q1 ping-pong in both layouts. [B,S,S], B=4,S=160 -> 102400
#define MAXQ 102400
#define MAXR 1024
__device__ __align__(16) float g_q1 [2][MAXQ];   // Q1[b,m,h]
__device__ __align__(16) float g_q1T[2][MAXQ];   // Q1[b,h,m]
__device__ int   g_excl[MAXQ];     // per (b,h): excluded t list (mask[b,t,h]==0 || t==h)
__device__ int   g_ecnt[MAXR];     // per (b,h): list length

// Pre-pass: build per-(b,h) exclusion list.
__global__ void excl_build_kernel(const int* __restrict__ mask, int S)
{
    __shared__ int cnt;
    int t = threadIdx.x;
    int h = blockIdx.x % S;
    int b = blockIdx.x / S;
    int row = b * S + h;
    if (t == 0) cnt = 0;
    __syncthreads();
    if (t < S) {
        bool ex = (mask[(b * S + t) * S + h] == 0) || (t == h);
        if (ex) {
            int slot = atomicAdd(&cnt, 1);
            g_excl[row * S + slot] = t;
        }
    }
    __syncthreads();
    if (t == 0) g_ecnt[row] = cnt;
}

// ============================================================================
// MODE 0 kernel: 3 pure score streams, register-capped (R8 config — measured fast)
// ============================================================================
__global__ void __launch_bounds__(256, 4)
mfvi_iter0(const float* __restrict__ se,
           const float* __restrict__ ss,
           const float* __restrict__ sc,
           const float* __restrict__ sg,
           const int* __restrict__ mask,
           int S, int outbuf)
{
    const int HT = 32;
    int ntile = (S + HT - 1) / HT;
    int blk = blockIdx.x;
    int htile = blk % ntile;
    int m     = (blk / ntile) % S;
    int b     = blk / (ntile * S);
    int warp = threadIdx.x >> 5, lane = threadIdx.x & 31;
    int g = lane >> 3, li = lane & 7;
    int h = htile * HT + warp * 4 + g;

    bool valid = (h < S);
    int FV = S >> 2;
    const long sbase = (((long)(b * S + m)) * S + h) * S;
    const float4* p_ss = (const float4*)(ss + sbase);
    const float4* p_sc = (const float4*)(sc + sbase);
    const float4* p_sg = (const float4*)(sg + sbase);

    float acc = 0.f;
    if (valid) {
        #pragma unroll 5
        for (int v = li; v < FV; v += 8) {
            float4 vss = __ldcs(p_ss + v);
            float4 vsc = __ldcs(p_sc + v);
            float4 vsg = __ldcs(p_sg + v);
            #pragma unroll
            for (int j = 0; j < 4; j++)
                acc += (&vss.x)[j] + (&vsc.x)[j] + (&vsg.x)[j];
        }
    }
    acc += __shfl_down_sync(0xffffffffu, acc, 4, 8);
    acc += __shfl_down_sync(0xffffffffu, acc, 2, 8);
    acc += __shfl_down_sync(0xffffffffu, acc, 1, 8);

    if (li == 0 && valid) {
        int idx = (b * S + m) * S + h;
        float f = 0.f;
        if (mask[idx] != 0) {
            acc *= 0.5f;
            int row = b * S + h;
            int cnt = g_ecnt[row];
            for (int i = 0; i < cnt; i++) {
                int t = g_excl[row * S + i];
                acc -= 0.5f * (ss[sbase + t] + sc[sbase + t] + sg[sbase + t]);
            }
            if (m != h)
                acc -= 0.5f * (ss[sbase + m] + sc[sbase + m] + sg[sbase + m]);
            f = acc;
        }
        float q = se[idx] + f;
        float q1v = 1.f / (1.f + expf(-q));
        g_q1 [outbuf][idx] = q1v;
        g_q1T[outbuf][(b * S + h) * S + m] = q1v;
    }
}

// ============================================================================
// MODE 1/2 kernel: deep-batch, NO register cap (R5 config — measured fast),
// compile-time S for full unroll. FINAL=1 -> write output probabilities.
// ============================================================================
template<int FINAL, int SS>
__global__ void __launch_bounds__(256)
mfvi_iter(const float* __restrict__ se,
          const float* __restrict__ ss,
          const float* __restrict__ sc,
          const float* __restrict__ sg,
          const int* __restrict__ mask,
          float* __restrict__ out,
          int parity)
{
    constexpr int HT = 32;
    constexpr int NTILE = (SS + HT - 1) / HT;
    constexpr int FV = SS >> 2;            // 40
    constexpr int KK = FV / 8;             // 5 chunks per 8-lane group

    int blk = blockIdx.x;
    int htile = blk % NTILE;
    int m     = (blk / NTILE) % SS;
    int b     = blk / (NTILE * SS);
    int warp = threadIdx.x >> 5, lane = threadIdx.x & 31;
    int g = lane >> 3, li = lane & 7;
    int h = htile * HT + warp * 4 + g;

    extern __shared__ float smbuf[];
    float* sm_row = smbuf;        // Q1[b,m,t]
    float* sm_col = smbuf + SS;   // Q1[b,t,m]

    const float* __restrict__ q1_in  = g_q1 [parity & 1];
    const float* __restrict__ q1T_in = g_q1T[parity & 1];

    {
        const float4* r4 = (const float4*)(q1_in  + (b * SS + m) * SS);
        const float4* c4 = (const float4*)(q1T_in + (b * SS + m) * SS);
        for (int i = threadIdx.x; i < 2 * FV; i += blockDim.x) {
            if (i < FV) ((float4*)sm_row)[i] = r4[i];
            else        ((float4*)sm_col)[i - FV] = c4[i - FV];
        }
        __syncthreads();
    }

    const long sbase = (((long)(b * SS + m)) * SS + h) * SS;
    const long hbase = ((long)(b * SS + h)) * SS;
    const float4* p_ss = (const float4*)(ss + sbase);
    const float4* p_sc = (const float4*)(sc + sbase);
    const float4* p_sg = (const float4*)(sg + sbase);
    const float4* p_qa = (const float4*)(q1T_in + hbase);
    const float4* srow = (const float4*)sm_row;
    const float4* scol = (const float4*)sm_col;

    float acc = 0.f;
    #pragma unroll
    for (int k = 0; k < KK; k++) {
        int v = li + 8 * k;
        float4 vss = __ldcs(p_ss + v);
        float4 vsc = __ldcs(p_sc + v);
        float4 vsg = __ldcs(p_sg + v);
        float4 vqa = __ldg(p_qa + v);
        float4 vr  = srow[v];
        float4 vc  = scol[v];
        #pragma unroll
        for (int j = 0; j < 4; j++) {
            acc += (&vss.x)[j] * (&vqa.x)[j];
            acc += (&vsc.x)[j] * (&vr.x)[j];
            acc += (&vsg.x)[j] * (&vc.x)[j];
        }
    }

    acc += __shfl_down_sync(0xffffffffu, acc, 4, 8);
    acc += __shfl_down_sync(0xffffffffu, acc, 2, 8);
    acc += __shfl_down_sync(0xffffffffu, acc, 1, 8);

    if (li == 0) {
        int idx = (b * SS + m) * SS + h;
        float f = 0.f;
        if (mask[idx] != 0) {
            int row = b * SS + h;
            int cnt = g_ecnt[row];
            for (int i = 0; i < cnt; i++) {
                int t = g_excl[row * SS + i];
                acc -= ss[sbase + t] * q1T_in[hbase + t]
                     + sc[sbase + t] * sm_row[t]
                     + sg[sbase + t] * sm_col[t];
            }
            if (m != h)
                acc -= ss[sbase + m] * q1T_in[hbase + m]
                     + sc[sbase + m] * sm_row[m]
                     + sg[sbase + m] * sm_col[m];
            f = acc;
        }
        float q = se[idx] + f;
        if (FINAL) {
            out[(long)idx * 2 + 0] = 1.f / (1.f + expf(q));
            out[(long)idx * 2 + 1] = 1.f / (1.f + expf(-q));
        } else {
            float q1v = 1.f / (1.f + expf(-q));
            int ob = (parity ^ 1) & 1;
            g_q1 [ob][idx] = q1v;
            g_q1T[ob][(b * SS + h) * SS + m] = q1v;
        }
    }
}

// ============================================================================
// Generic fallback for S != 160 (R8 kernel, MODE 1/2)
// ============================================================================
template<int FINAL>
__global__ void __launch_bounds__(256, 4)
mfvi_fallback(const float* __restrict__ se,
              const float* __restrict__ ss,
              const float* __restrict__ sc,
              const float* __restrict__ sg,
              const int* __restrict__ mask,
              float* __restrict__ out,
              int S, int parity)
{
    const int HT = 32;
    int ntile = (S + HT - 1) / HT;
    int blk = blockIdx.x;
    int htile = blk % ntile;
    int m     = (blk / ntile) % S;
    int b     = blk / (ntile * S);
    int warp = threadIdx.x >> 5, lane = threadIdx.x & 31;
    int g = lane >> 3, li = lane & 7;
    int h = htile * HT + warp * 4 + g;

    extern __shared__ float smbuf[];
    float* sm_row = smbuf;
    float* sm_col = smbuf + S;

    const float* __restrict__ q1_in  = g_q1 [parity & 1];
    const float* __restrict__ q1T_in = g_q1T[parity & 1];

    {
        int nv = S >> 2;
        const float4* r4 = (const float4*)(q1_in  + (b * S + m) * S);
        const float4* c4 = (const float4*)(q1T_in + (b * S + m) * S);
        for (int i = threadIdx.x; i < 2 * nv; i += blockDim.x) {
            if (i < nv) ((float4*)sm_row)[i] = r4[i];
            else        ((float4*)sm_col)[i - nv] = c4[i - nv];
        }
        __syncthreads();
    }

    bool valid = (h < S);
    int FV = S >> 2;
    const long sbase = (((long)(b * S + m)) * S + h) * S;
    const long hbase = ((long)(b * S + h)) * S;
    const float4* p_ss = (const float4*)(ss + sbase);
    const float4* p_sc = (const float4*)(sc + sbase);
    const float4* p_sg = (const float4*)(sg + sbase);
    const float4* p_qa = (const float4*)(q1T_in + hbase);
    const float4* srow = (const float4*)sm_row;
    const float4* scol = (const float4*)sm_col;

    float acc = 0.f;
    if (valid) {
        #pragma unroll 5
        for (int v = li; v < FV; v += 8) {
            float4 vss = __ldcs(p_ss + v);
            float4 vsc = __ldcs(p_sc + v);
            float4 vsg = __ldcs(p_sg + v);
            float4 vqa = p_qa[v];
            float4 vr  = srow[v];
            float4 vc  = scol[v];
            #pragma unroll
            for (int j = 0; j < 4; j++) {
                acc += (&vss.x)[j] * (&vqa.x)[j];
                acc += (&vsc.x)[j] * (&vr.x)[j];
                acc += (&vsg.x)[j] * (&vc.x)[j];
            }
        }
    }
    acc += __shfl_down_sync(0xffffffffu, acc, 4, 8);
    acc += __shfl_down_sync(0xffffffffu, acc, 2, 8);
    acc += __shfl_down_sync(0xffffffffu, acc, 1, 8);

    if (li == 0 && valid) {
        int idx = (b * S + m) * S + h;
        float f = 0.f;
        if (mask[idx] != 0) {
            int row = b * S + h;
            int cnt = g_ecnt[row];
            for (int i = 0; i < cnt; i++) {
                int t = g_excl[row * S + i];
                acc -= ss[sbase + t] * q1T_in[hbase + t]
                     + sc[sbase + t] * sm_row[t]
                     + sg[sbase + t] * sm_col[t];
            }
            if (m != h)
                acc -= ss[sbase + m] * q1T_in[hbase + m]
                     + sc[sbase + m] * sm_row[m]
                     + sg[sbase + m] * sm_col[m];
            f = acc;
        }
        float q = se[idx] + f;
        if (FINAL) {
            out[(long)idx * 2 + 0] = 1.f / (1.f + expf(q));
            out[(long)idx * 2 + 1] = 1.f / (1.f + expf(-q));
        } else {
            float q1v = 1.f / (1.f + expf(-q));
            int ob = (parity ^ 1) & 1;
            g_q1 [ob][idx] = q1v;
            g_q1T[ob][(b * S + h) * S + m] = q1v;
        }
    }
}

extern "C" void kernel_launch(void* const* d_in, const int* in_sizes, int n_in,
                              void* d_out, int out_size)
{
    const float* se = (const float*)d_in[0];
    const float* ss = (const float*)d_in[1];
    const float* sc = (const float*)d_in[2];
    const float* sg = (const float*)d_in[3];
    const int* mask = (const int*)d_in[4];
    float* out = (float*)d_out;

    int BSS = in_sizes[0];                  // B*S*S
    int S = in_sizes[1] / BSS;              // (B*S^3)/(B*S^2)
    int B = BSS / (S * S);

    excl_build_kernel<<<B * S, (S + 31) & ~31>>>(mask, S);

    int ntile = (S + 31) / 32;
    dim3 grid(B * S * ntile);
    size_t smem = 2 * (size_t)S * sizeof(float);

    // iter 1 (Q1 = 0.5) -> q1 buffer 0
    mfvi_iter0<<<grid, 256>>>(se, ss, sc, sg, mask, S, 0);

    if (S == 160) {
        // iter 2: read buf 0, write buf 1
        mfvi_iter<0, 160><<<grid, 256, smem>>>(se, ss, sc, sg, mask, out, 0);
        // iter 3: read buf 1, write output
        mfvi_iter<1, 160><<<grid, 256, smem>>>(se, ss, sc, sg, mask, out, 1);
    } else {
        mfvi_fallback<0><<<grid, 256, smem>>>(se, ss, sc, sg, mask, out, S, 0);
        mfvi_fallback<1><<<grid, 256, smem>>>(se, ss, sc, sg, mask, out, S, 1);
    }
}

// round 13
// speedup vs baseline: 1.8920x; 1.0309x over previous
#include <cuda_runtime.h>
#include <cuda_fp16.h>
#include <math.h>
#include <stdint.h>

// Scratch: Q1 ping-pong in both layouts. [B,S,S], B=4,S=160 -> 102400
#define MAXQ 102400
#define MAXR 1024
#define MAXE 16384000              // B*S^3 = 4*160^3
__device__ __align__(16) float g_q1 [2][MAXQ];   // Q1[b,m,h]
__device__ __align__(16) float g_q1T[2][MAXQ];   // Q1[b,h,m]
__device__ int   g_excl[MAXQ];     // per (b,h): excluded t list (mask[b,t,h]==0 || t==h)
__device__ int   g_ecnt[MAXR];     // per (b,h): list length
// fp16 copies of the score tensors (written by iter0, read by iters 2/3)
__device__ __align__(16) __half g_hss[MAXE];
__device__ __align__(16) __half g_hsc[MAXE];
__device__ __align__(16) __half g_hsg[MAXE];

// Pre-pass: build per-(b,h) exclusion list.
__global__ void excl_build_kernel(const int* __restrict__ mask, int S)
{
    __shared__ int cnt;
    int t = threadIdx.x;
    int h = blockIdx.x % S;
    int b = blockIdx.x / S;
    int row = b * S + h;
    if (t == 0) cnt = 0;
    __syncthreads();
    if (t < S) {
        bool ex = (mask[(b * S + t) * S + h] == 0) || (t == h);
        if (ex) {
            int slot = atomicAdd(&cnt, 1);
            g_excl[row * S + slot] = t;
        }
    }
    __syncthreads();
    if (t == 0) g_ecnt[row] = cnt;
}

// ============================================================================
// Iter 1 (Q1 = 0.5), fused fp32->fp16 conversion of the three score tensors.
// ============================================================================
template<int SS>
__global__ void __launch_bounds__(256, 4)
mfvi_iter0_conv(const float* __restrict__ se,
                const float* __restrict__ ss,
                const float* __restrict__ sc,
                const float* __restrict__ sg,
                const int* __restrict__ mask,
                int outbuf)
{
    constexpr int HT = 32;
    constexpr int NTILE = SS / HT;
    constexpr int FV = SS >> 2;
    constexpr int KK = FV / 8;     // 5

    int blk = blockIdx.x;
    int htile = blk % NTILE;
    int m     = (blk / NTILE) % SS;
    int b     = blk / (NTILE * SS);
    int warp = threadIdx.x >> 5, lane = threadIdx.x & 31;
    int g = lane >> 3, li = lane & 7;
    int h = htile * HT + warp * 4 + g;

    const long sbase = (((long)(b * SS + m)) * SS + h) * SS;
    const float4* p_ss = (const float4*)(ss + sbase);
    const float4* p_sc = (const float4*)(sc + sbase);
    const float4* p_sg = (const float4*)(sg + sbase);
    uint2* w_ss = (uint2*)(g_hss + sbase);
    uint2* w_sc = (uint2*)(g_hsc + sbase);
    uint2* w_sg = (uint2*)(g_hsg + sbase);

    float acc = 0.f;
    #pragma unroll
    for (int k = 0; k < KK; k++) {
        int v = li + 8 * k;
        float4 vss = __ldcs(p_ss + v);
        float4 vsc = __ldcs(p_sc + v);
        float4 vsg = __ldcs(p_sg + v);
        #pragma unroll
        for (int j = 0; j < 4; j++)
            acc += (&vss.x)[j] + (&vsc.x)[j] + (&vsg.x)[j];
        __half2 a0 = __floats2half2_rn(vss.x, vss.y), a1 = __floats2half2_rn(vss.z, vss.w);
        __half2 b0 = __floats2half2_rn(vsc.x, vsc.y), b1 = __floats2half2_rn(vsc.z, vsc.w);
        __half2 c0 = __floats2half2_rn(vsg.x, vsg.y), c1 = __floats2half2_rn(vsg.z, vsg.w);
        uint2 u;
        u.x = *(unsigned*)&a0; u.y = *(unsigned*)&a1; __stcs(w_ss + v, u);
        u.x = *(unsigned*)&b0; u.y = *(unsigned*)&b1; __stcs(w_sc + v, u);
        u.x = *(unsigned*)&c0; u.y = *(unsigned*)&c1; __stcs(w_sg + v, u);
    }
    acc += __shfl_down_sync(0xffffffffu, acc, 4, 8);
    acc += __shfl_down_sync(0xffffffffu, acc, 2, 8);
    acc += __shfl_down_sync(0xffffffffu, acc, 1, 8);

    if (li == 0) {
        int idx = (b * SS + m) * SS + h;
        float f = 0.f;
        if (mask[idx] != 0) {
            acc *= 0.5f;
            int row = b * SS + h;
            int cnt = g_ecnt[row];
            for (int i = 0; i < cnt; i++) {
                int t = g_excl[row * SS + i];
                acc -= 0.5f * (ss[sbase + t] + sc[sbase + t] + sg[sbase + t]);
            }
            if (m != h)
                acc -= 0.5f * (ss[sbase + m] + sc[sbase + m] + sg[sbase + m]);
            f = acc;
        }
        float q = se[idx] + f;
        float q1v = 1.f / (1.f + expf(-q));
        g_q1 [outbuf][idx] = q1v;
        g_q1T[outbuf][(b * SS + h) * SS + m] = q1v;
    }
}

// unpack 8 halves (uint4) -> 8 floats
__device__ __forceinline__ void h8f(const uint4& u, float* f) {
    float2 t;
    t = __half22float2(*(const __half2*)&u.x); f[0] = t.x; f[1] = t.y;
    t = __half22float2(*(const __half2*)&u.y); f[2] = t.x; f[3] = t.y;
    t = __half22float2(*(const __half2*)&u.z); f[4] = t.x; f[5] = t.y;
    t = __half22float2(*(const __half2*)&u.w); f[6] = t.x; f[7] = t.y;
}

// ============================================================================
// Iters 2/3: fp16 score streams. 128 threads, 4-lane groups, 32 h-rows/block.
// ============================================================================
template<int FINAL, int SS>
__global__ void __launch_bounds__(128)
mfvi_iter_h(const float* __restrict__ se,
            const int* __restrict__ mask,
            float* __restrict__ out,
            int parity)
{
    constexpr int HT = 32;
    constexpr int NTILE = SS / HT;
    constexpr int FV = SS >> 2;    // 40 float4 per row
    constexpr int CH = SS / 8;     // 20 uint4(half8) chunks per row
    constexpr int KK = CH / 4;     // 5 chunks per 4-lane group lane

    int blk = blockIdx.x;
    int htile = blk % NTILE;
    int m     = (blk / NTILE) % SS;
    int b     = blk / (NTILE * SS);
    int tid = threadIdx.x;
    int w = tid >> 5, lane = tid & 31;
    int g2 = lane >> 2, li4 = lane & 3;
    int rt = w * 8 + g2;
    int h = htile * HT + rt;

    extern __shared__ float smbuf[];
    float* sm_row = smbuf;        // Q1[b,m,t]
    float* sm_col = smbuf + SS;   // Q1[b,t,m]

    const float* __restrict__ q1_in  = g_q1 [parity & 1];
    const float* __restrict__ q1T_in = g_q1T[parity & 1];

    {
        const float4* r4 = (const float4*)(q1_in  + (b * SS + m) * SS);
        const float4* c4 = (const float4*)(q1T_in + (b * SS + m) * SS);
        for (int i = tid; i < 2 * FV; i += 128) {
            if (i < FV) ((float4*)sm_row)[i] = r4[i];
            else        ((float4*)sm_col)[i - FV] = c4[i - FV];
        }
        __syncthreads();
    }

    const long sbase = (((long)(b * SS + m)) * SS + h) * SS;
    const long hbase = ((long)(b * SS + h)) * SS;
    const uint4* pss = (const uint4*)(g_hss + sbase);
    const uint4* psc = (const uint4*)(g_hsc + sbase);
    const uint4* psg = (const uint4*)(g_hsg + sbase);
    const float4* pqa = (const float4*)(q1T_in + hbase);
    const float4* srow = (const float4*)sm_row;
    const float4* scol = (const float4*)sm_col;

    float acc = 0.f;
    #pragma unroll
    for (int k = 0; k < KK; k++) {
        int c = li4 + 4 * k;
        uint4 ua = __ldcs(pss + c);
        uint4 ub = __ldcs(psc + c);
        uint4 uc = __ldcs(psg + c);
        float4 q0 = __ldg(pqa + 2 * c), q1v = __ldg(pqa + 2 * c + 1);
        float4 r0 = srow[2 * c], r1 = srow[2 * c + 1];
        float4 c0 = scol[2 * c], c1 = scol[2 * c + 1];
        float fa[8], fb[8], fc[8];
        h8f(ua, fa); h8f(ub, fb); h8f(uc, fc);
        float qv[8] = {q0.x, q0.y, q0.z, q0.w, q1v.x, q1v.y, q1v.z, q1v.w};
        float rv[8] = {r0.x, r0.y, r0.z, r0.w, r1.x, r1.y, r1.z, r1.w};
        float cv[8] = {c0.x, c0.y, c0.z, c0.w, c1.x, c1.y, c1.z, c1.w};
        #pragma unroll
        for (int j = 0; j < 8; j++) {
            acc += fa[j] * qv[j];
            acc += fb[j] * rv[j];
            acc += fc[j] * cv[j];
        }
    }

    acc += __shfl_down_sync(0xffffffffu, acc, 2, 4);
    acc += __shfl_down_sync(0xffffffffu, acc, 1, 4);

    if (li4 == 0) {
        int idx = (b * SS + m) * SS + h;
        float f = 0.f;
        if (mask[idx] != 0) {
            int row = b * SS + h;
            int cnt = g_ecnt[row];
            for (int i = 0; i < cnt; i++) {
                int t = g_excl[row * SS + i];
                acc -= __half2float(g_hss[sbase + t]) * q1T_in[hbase + t]
                     + __half2float(g_hsc[sbase + t]) * sm_row[t]
                     + __half2float(g_hsg[sbase + t]) * sm_col[t];
            }
            if (m != h)
                acc -= __half2float(g_hss[sbase + m]) * q1T_in[hbase + m]
                     + __half2float(g_hsc[sbase + m]) * sm_row[m]
                     + __half2float(g_hsg[sbase + m]) * sm_col[m];
            f = acc;
        }
        float q = se[idx] + f;
        if (FINAL) {
            out[(long)idx * 2 + 0] = 1.f / (1.f + expf(q));
            out[(long)idx * 2 + 1] = 1.f / (1.f + expf(-q));
        } else {
            float q1v = 1.f / (1.f + expf(-q));
            int ob = (parity ^ 1) & 1;
            g_q1 [ob][idx] = q1v;
            g_q1T[ob][(b * SS + h) * SS + m] = q1v;
        }
    }
}

// ============================================================================
// Generic fp32 fallback for S != 160 (R12 kernels)
// ============================================================================
__global__ void __launch_bounds__(256, 4)
mfvi_iter0_gen(const float* __restrict__ se,
               const float* __restrict__ ss,
               const float* __restrict__ sc,
               const float* __restrict__ sg,
               const int* __restrict__ mask,
               int S, int outbuf)
{
    const int HT = 32;
    int ntile = (S + HT - 1) / HT;
    int blk = blockIdx.x;
    int htile = blk % ntile;
    int m     = (blk / ntile) % S;
    int b     = blk / (ntile * S);
    int warp = threadIdx.x >> 5, lane = threadIdx.x & 31;
    int g = lane >> 3, li = lane & 7;
    int h = htile * HT + warp * 4 + g;
    bool valid = (h < S);
    int FV = S >> 2;
    const long sbase = (((long)(b * S + m)) * S + h) * S;
    const float4* p_ss = (const float4*)(ss + sbase);
    const float4* p_sc = (const float4*)(sc + sbase);
    const float4* p_sg = (const float4*)(sg + sbase);

    float acc = 0.f;
    if (valid) {
        #pragma unroll 5
        for (int v = li; v < FV; v += 8) {
            float4 vss = __ldcs(p_ss + v);
            float4 vsc = __ldcs(p_sc + v);
            float4 vsg = __ldcs(p_sg + v);
            #pragma unroll
            for (int j = 0; j < 4; j++)
                acc += (&vss.x)[j] + (&vsc.x)[j] + (&vsg.x)[j];
        }
        for (int t = (S & ~3) + li; t < S; t += 8)
            acc += ss[sbase + t] + sc[sbase + t] + sg[sbase + t];
    }
    acc += __shfl_down_sync(0xffffffffu, acc, 4, 8);
    acc += __shfl_down_sync(0xffffffffu, acc, 2, 8);
    acc += __shfl_down_sync(0xffffffffu, acc, 1, 8);
    if (li == 0 && valid) {
        int idx = (b * S + m) * S + h;
        float f = 0.f;
        if (mask[idx] != 0) {
            acc *= 0.5f;
            int row = b * S + h;
            int cnt = g_ecnt[row];
            for (int i = 0; i < cnt; i++) {
                int t = g_excl[row * S + i];
                acc -= 0.5f * (ss[sbase + t] + sc[sbase + t] + sg[sbase + t]);
            }
            if (m != h)
                acc -= 0.5f * (ss[sbase + m] + sc[sbase + m] + sg[sbase + m]);
            f = acc;
        }
        float q = se[idx] + f;
        float q1v = 1.f / (1.f + expf(-q));
        g_q1 [outbuf][idx] = q1v;
        g_q1T[outbuf][(b * S + h) * S + m] = q1v;
    }
}

template<int FINAL>
__global__ void __launch_bounds__(256, 4)
mfvi_fallback(const float* __restrict__ se,
              const float* __restrict__ ss,
              const float* __restrict__ sc,
              const float* __restrict__ sg,
              const int* __restrict__ mask,
              float* __restrict__ out,
              int S, int parity)
{
    const int HT = 32;
    int ntile = (S + HT - 1) / HT;
    int blk = blockIdx.x;
    int htile = blk % ntile;
    int m     = (blk / ntile) % S;
    int b     = blk / (ntile * S);
    int warp = threadIdx.x >> 5, lane = threadIdx.x & 31;
    int g = lane >> 3, li = lane & 7;
    int h = htile * HT + warp * 4 + g;

    extern __shared__ float smbuf[];
    float* sm_row = smbuf;
    float* sm_col = smbuf + S;
    const float* __restrict__ q1_in  = g_q1 [parity & 1];
    const float* __restrict__ q1T_in = g_q1T[parity & 1];
    for (int i = threadIdx.x; i < 2 * S; i += blockDim.x) {
        if (i < S) sm_row[i] = q1_in[(b * S + m) * S + i];
        else       sm_col[i - S] = q1T_in[(b * S + m) * S + (i - S)];
    }
    __syncthreads();

    bool valid = (h < S);
    const long sbase = (((long)(b * S + m)) * S + h) * S;
    const long hbase = ((long)(b * S + h)) * S;
    float acc = 0.f;
    if (valid) {
        for (int t = li; t < S; t += 8)
            acc += ss[sbase + t] * q1T_in[hbase + t]
                 + sc[sbase + t] * sm_row[t]
                 + sg[sbase + t] * sm_col[t];
    }
    acc += __shfl_down_sync(0xffffffffu, acc, 4, 8);
    acc += __shfl_down_sync(0xffffffffu, acc, 2, 8);
    acc += __shfl_down_sync(0xffffffffu, acc, 1, 8);
    if (li == 0 && valid) {
        int idx = (b * S + m) * S + h;
        float f = 0.f;
        if (mask[idx] != 0) {
            int row = b * S + h;
            int cnt = g_ecnt[row];
            for (int i = 0; i < cnt; i++) {
                int t = g_excl[row * S + i];
                acc -= ss[sbase + t] * q1T_in[hbase + t]
                     + sc[sbase + t] * sm_row[t]
                     + sg[sbase + t] * sm_col[t];
            }
            if (m != h)
                acc -= ss[sbase + m] * q1T_in[hbase + m]
                     + sc[sbase + m] * sm_row[m]
                     + sg[sbase + m] * sm_col[m];
            f = acc;
        }
        float q = se[idx] + f;
        if (FINAL) {
            out[(long)idx * 2 + 0] = 1.f / (1.f + expf(q));
            out[(long)idx * 2 + 1] = 1.f / (1.f + expf(-q));
        } else {
            float q1v = 1.f / (1.f + expf(-q));
            int ob = (parity ^ 1) & 1;
            g_q1 [ob][idx] = q1v;
            g_q1T[ob][(b * S + h) * S + m] = q1v;
        }
    }
}

extern "C" void kernel_launch(void* const* d_in, const int* in_sizes, int n_in,
                              void* d_out, int out_size)
{
    const float* se = (const float*)d_in[0];
    const float* ss = (const float*)d_in[1];
    const float* sc = (const float*)d_in[2];
    const float* sg = (const float*)d_in[3];
    const int* mask = (const int*)d_in[4];
    float* out = (float*)d_out;

    int BSS = in_sizes[0];                  // B*S*S
    int S = in_sizes[1] / BSS;              // (B*S^3)/(B*S^2)
    int B = BSS / (S * S);

    excl_build_kernel<<<B * S, (S + 31) & ~31>>>(mask, S);

    int ntile = (S + 31) / 32;
    dim3 grid(B * S * ntile);
    size_t smem = 2 * (size_t)S * sizeof(float);

    if (S == 160) {
        // iter 1: fp32 sum (Q1=0.5) + fp16 conversion of scores -> buf 0
        mfvi_iter0_conv<160><<<grid, 256>>>(se, ss, sc, sg, mask, 0);
        // iter 2: fp16 streams, read buf 0, write buf 1
        mfvi_iter_h<0, 160><<<grid, 128, smem>>>(se, mask, out, 0);
        // iter 3: fp16 streams, read buf 1, write output
        mfvi_iter_h<1, 160><<<grid, 128, smem>>>(se, mask, out, 1);
    } else {
        mfvi_iter0_gen<<<grid, 256>>>(se, ss, sc, sg, mask, S, 0);
        mfvi_fallback<0><<<grid, 256, smem>>>(se, ss, sc, sg, mask, out, S, 0);
        mfvi_fallback<1><<<grid, 256, smem>>>(se, ss, sc, sg, mask, out, S, 1);
    }
}